// round 14
// baseline (speedup 1.0000x reference)
#include <cuda_runtime.h>
#include <cuda_fp16.h>
#include <cstdint>

// ---------------- problem geometry ----------------
static constexpr int MDIM = 8192;
static constexpr int NDIM = 4096;
static constexpr int KDIM = 4096;

static constexpr int BM = 128;
static constexpr int BN = 128;
static constexpr int BKC = 32;               // fp16 k elems per chunk (64 B rows)
static constexpr int NKC = KDIM / BKC;       // 128 chunks
static constexpr int STAGES = 6;
static constexpr int NTHREADS = 128;         // 4 warps, warp tile 64x64

static constexpr int ROW_B = 64;                         // 64 B per row, no padding
static constexpr int A_TILE_B = BM * ROW_B;              // 8192 bytes
static constexpr int B_TILE_B = BN * ROW_B;              // 8192 bytes
static constexpr int STAGE_B = A_TILE_B + B_TILE_B;      // 16384
static constexpr int MASK_WORDS = 256 * 8;               // [k_block][o_word] bits over o
static constexpr int MASK_B = MASK_WORDS * 4;            // 8192 bytes
static constexpr int SMEM_BYTES = STAGES * STAGE_B + MASK_B;  // 106496 -> 2 CTAs/SM

// ---------------- device scratch (allocation-free) ----------------
static __device__ __half g_xh[(size_t)MDIM * KDIM];
static __device__ __half g_wh[(size_t)NDIM * KDIM];
static __device__ uint32_t g_mask[MASK_WORDS];

// ---------------- PTX helpers (base-target, sm_80-era) ----------------
__device__ __forceinline__ uint32_t smem_u32(const void* p) {
    uint32_t a;
    asm("{ .reg .u64 t; cvta.to.shared.u64 t, %1; cvt.u32.u64 %0, t; }" : "=r"(a) : "l"(p));
    return a;
}

#define CP_ASYNC16(dst, src) \
    asm volatile("cp.async.cg.shared.global [%0], [%1], 16;" :: "r"(dst), "l"(src) : "memory")
#define CP_COMMIT() asm volatile("cp.async.commit_group;" ::: "memory")
#define CP_WAIT(n)  asm volatile("cp.async.wait_group %0;" :: "n"(n) : "memory")

#define LDSM4(r0, r1, r2, r3, addr)                                        \
    asm volatile("ldmatrix.sync.aligned.m8n8.x4.shared.b16 {%0,%1,%2,%3}, [%4];" \
                 : "=r"(r0), "=r"(r1), "=r"(r2), "=r"(r3) : "r"(addr))

#define MMA16816(c, a, b0, b1)                                             \
    asm volatile(                                                          \
        "mma.sync.aligned.m16n8k16.row.col.f32.f16.f16.f32 "               \
        "{%0,%1,%2,%3}, {%4,%5,%6,%7}, {%8,%9}, {%0,%1,%2,%3};"            \
        : "+f"((c)[0]), "+f"((c)[1]), "+f"((c)[2]), "+f"((c)[3])           \
        : "r"((a)[0]), "r"((a)[1]), "r"((a)[2]), "r"((a)[3]),              \
          "r"(b0), "r"(b1))

// ---------------- zero kernel (capture-safe; no memset API) ----------------
__global__ void __launch_bounds__(256) k_zero(uint32_t* __restrict__ p, int n) {
    int i = blockIdx.x * blockDim.x + threadIdx.x;
    if (i < n) p[i] = 0u;
}

// ---------------- conversion kernel: fp32 -> fp16 ----------------
__global__ void __launch_bounds__(256) k_cvt(const float* __restrict__ src,
                                             __half* __restrict__ dst, int n4) {
    int i = blockIdx.x * blockDim.x + threadIdx.x;
    if (i >= n4) return;
    float4 v = reinterpret_cast<const float4*>(src)[i];
    __half2 p0(__float2half_rn(v.x), __float2half_rn(v.y));
    __half2 p1(__float2half_rn(v.z), __float2half_rn(v.w));
    uint2 o;
    o.x = *reinterpret_cast<uint32_t*>(&p0);
    o.y = *reinterpret_cast<uint32_t*>(&p1);
    reinterpret_cast<uint2*>(dst)[i] = o;
}

// ---------------- block-mask kernel (fp16 input): one warp per 16x16 block ----------------
__global__ void __launch_bounds__(256) k_mask(const __half* __restrict__ wh,
                                              uint32_t* __restrict__ maskT) {
    int wg = (blockIdx.x * blockDim.x + threadIdx.x) >> 5;   // 0 .. 65535
    if (wg >= 256 * 256) return;
    int ob = wg >> 8;      // output-feature block (row block of W)
    int kb = wg & 255;     // k block (col block of W)
    int lane = threadIdx.x & 31;
    // lane covers row ob*16 + (lane>>1), 8 halfs at col kb*16 + (lane&1)*8
    const __half* base = wh + (size_t)(ob * 16 + (lane >> 1)) * KDIM + kb * 16 + (lane & 1) * 8;
    uint4 v = *reinterpret_cast<const uint4*>(base);
    // numeric zero test: clear sign bits (masked blocks can hold -0.0)
    uint32_t nzw = (v.x | v.y | v.z | v.w) & 0x7FFF7FFFu;
    uint32_t ball = __ballot_sync(0xFFFFFFFFu, nzw != 0u);
    if (lane == 0 && ball)
        atomicOr(&maskT[kb * 8 + (ob >> 5)], 1u << (ob & 31));
}

// ---------------- GEMM: 4 warps x (64x64), swizzled smem, sparse B loads + MMA skip ----------------
__global__ void __launch_bounds__(NTHREADS, 2) k_gemm(
    const __half* __restrict__ xh, const __half* __restrict__ wh,
    const uint32_t* __restrict__ maskT,
    const float* __restrict__ bias, float* __restrict__ out) {
    extern __shared__ char smem[];
    const uint32_t sb = smem_u32(smem);
    uint32_t* s_mask = reinterpret_cast<uint32_t*>(smem + STAGES * STAGE_B);

    const int tid = threadIdx.x;
    const int wid = tid >> 5;     // 0..3
    const int lane = tid & 31;
    const int warp_m = wid & 1;   // 0..1 -> 64 rows
    const int warp_n = wid >> 1;  // 0..1 -> 64 cols

    // tile mapping with L2 supergrouping
    constexpr int NPN = NDIM / BN;  // 32
    constexpr int GROUP_M = 8;
    int pid = blockIdx.x;
    int npg = GROUP_M * NPN;        // 256
    int pm = (pid / npg) * GROUP_M + (pid % npg) % GROUP_M;
    int pn = (pid % npg) / GROUP_M;

    const int ldrow = tid >> 2;   // 0..31
    const int ldseg = tid & 3;    // 0..3
    // swizzled destination segment (r0 multiples of 32 keep (r>>1)&3 invariant)
    const uint32_t st_off = (uint32_t)((ldseg ^ ((ldrow >> 1) & 3)) * 16);

    // per-thread B-block mask addressing: this thread's B load at (row r0+ldrow, kseg ldseg)
    // covers o-block pn*8 + (r0+ldrow)/16 and k-block it*2 + (ldseg>>1).
    // o-blocks pn*8..pn*8+7 always share one 32-bit word: word = pn>>2, bit base (pn&3)*8.
    const int m_sks = ldseg >> 1;                         // k-block within chunk
    const int m_word = pn >> 2;
    const int m_shb = (pn & 3) * 8 + (ldrow >> 4);        // + r0/16 per load

    auto a_s = [&](int s) { return sb + (uint32_t)s * STAGE_B; };
    auto b_s = [&](int s) { return sb + (uint32_t)s * STAGE_B + A_TILE_B; };

    const __half* gA = xh + (size_t)(pm * BM) * KDIM;
    const __half* gB = wh + (size_t)(pn * BN) * KDIM;

    // stage the block mask (2048 words) into smem BEFORE any issue_stage reads it
    #pragma unroll
    for (int i = 0; i < MASK_WORDS / NTHREADS; i++)
        s_mask[i * NTHREADS + tid] = maskT[i * NTHREADS + tid];
    __syncthreads();

    auto issue_stage = [&](int it, int buf) {
        if (it < NKC) {
            int k0 = it * BKC;
            uint32_t dsta = a_s(buf), dstb = b_s(buf);
            uint32_t mw = s_mask[(it * 2 + m_sks) * 8 + m_word];
            #pragma unroll
            for (int r0 = 0; r0 < BM; r0 += 32) {
                int r = r0 + ldrow;
                uint32_t doff = (uint32_t)(r * ROW_B) + st_off;
                CP_ASYNC16(dsta + doff, gA + (size_t)r * KDIM + k0 + ldseg * 8);
                // skip B load when its 16x16 weight block is zero (data never consumed)
                if ((mw >> (m_shb + r0 / 16)) & 1u)
                    CP_ASYNC16(dstb + doff, gB + (size_t)r * KDIM + k0 + ldseg * 8);
            }
        }
        CP_COMMIT();
    };

    // ---- ldmatrix lane addressing (swizzled) ----
    const int sA = ((lane & 15) >> 1) & 3;
    const uint32_t a_row_off = (uint32_t)((warp_m * 64 + (lane & 15)) * ROW_B);
    const uint32_t segA_ks0 = (uint32_t)((((lane >> 4)) ^ sA) * 16);
    const uint32_t segA_ks1 = (uint32_t)(((2 + (lane >> 4)) ^ sA) * 16);
    const int sB = ((((lane >> 4) * 8) + (lane & 7)) >> 1) & 3;
    const uint32_t b_row_off =
        (uint32_t)((warp_n * 64 + (lane >> 4) * 8 + (lane & 7)) * ROW_B);
    const uint32_t segB_ks0 = (uint32_t)(((((lane >> 3) & 1)) ^ sB) * 16);
    const uint32_t segB_ks1 = (uint32_t)(((2 + ((lane >> 3) & 1)) ^ sB) * 16);

    // warp's o-block word index and bit shift (4 consecutive bits, never straddles)
    const int nblk0 = pn * 8 + warp_n * 4;
    const int word_idx = nblk0 >> 5;
    const int sh = nblk0 & 31;

    float acc[4][8][4];
    #pragma unroll
    for (int i = 0; i < 4; i++)
        #pragma unroll
        for (int j = 0; j < 8; j++)
            #pragma unroll
            for (int t = 0; t < 4; t++) acc[i][j][t] = 0.0f;

    #pragma unroll
    for (int s = 0; s < STAGES - 1; s++) issue_stage(s, s);

    for (int it = 0; it < NKC; ++it) {
        CP_WAIT(STAGES - 2);
        __syncthreads();

        // fetch mask words early (off the MMA critical path)
        uint32_t bits0 = (s_mask[(it * 2 + 0) * 8 + word_idx] >> sh) & 15u;
        uint32_t bits1 = (s_mask[(it * 2 + 1) * 8 + word_idx] >> sh) & 15u;

        issue_stage(it + STAGES - 1, (it + STAGES - 1) % STAGES);

        int buf = it % STAGES;
        uint32_t Ab = a_s(buf);
        uint32_t Bb = b_s(buf);

        #pragma unroll
        for (int ks = 0; ks < 2; ks++) {
            const uint32_t bits = ks ? bits1 : bits0;
            const uint32_t segA = ks ? segA_ks1 : segA_ks0;
            const uint32_t segB = ks ? segB_ks1 : segB_ks0;

            // dense LDSM stream (stale B data for skipped blocks is never consumed)
            uint32_t br[4][4];
            #pragma unroll
            for (int p = 0; p < 4; p++)
                LDSM4(br[p][0], br[p][1], br[p][2], br[p][3],
                      Bb + b_row_off + (uint32_t)(p * 16 * ROW_B) + segB);

            uint32_t ar[4][4];
            #pragma unroll
            for (int ms = 0; ms < 4; ms++)
                LDSM4(ar[ms][0], ar[ms][1], ar[ms][2], ar[ms][3],
                      Ab + a_row_off + (uint32_t)(ms * 16 * ROW_B) + segA);

            // predicated compute: skip 8-MMA group when the 16x16 weight block is zero
            #pragma unroll
            for (int p = 0; p < 4; p++) {
                if (bits & (1u << p)) {
                    #pragma unroll
                    for (int ms = 0; ms < 4; ms++) {
                        MMA16816(acc[ms][2 * p],     ar[ms], br[p][0], br[p][1]);
                        MMA16816(acc[ms][2 * p + 1], ar[ms], br[p][2], br[p][3]);
                    }
                }
            }
        }
    }

    // epilogue: acc + bias -> out
    const int m_base = pm * BM + warp_m * 64 + (lane >> 2);
    const int n_base = pn * BN + warp_n * 64 + (lane & 3) * 2;
    #pragma unroll
    for (int ns = 0; ns < 8; ns++) {
        int col = n_base + ns * 8;
        float bv0 = __ldg(&bias[col]);
        float bv1 = __ldg(&bias[col + 1]);
        #pragma unroll
        for (int ms = 0; ms < 4; ms++) {
            int r0 = m_base + ms * 16;
            float2 v0, v1;
            v0.x = acc[ms][ns][0] + bv0;
            v0.y = acc[ms][ns][1] + bv1;
            v1.x = acc[ms][ns][2] + bv0;
            v1.y = acc[ms][ns][3] + bv1;
            *reinterpret_cast<float2*>(out + (size_t)r0 * NDIM + col) = v0;
            *reinterpret_cast<float2*>(out + (size_t)(r0 + 8) * NDIM + col) = v1;
        }
    }
}

// ---------------- host side ----------------
extern "C" void kernel_launch(void* const* d_in, const int* in_sizes, int n_in,
                              void* d_out, int out_size) {
    const float* x    = (const float*)d_in[0];
    const float* w    = (const float*)d_in[1];
    const float* bias = (const float*)d_in[2];
    float* out        = (float*)d_out;

    void *p_xh, *p_wh, *p_mask;
    cudaGetSymbolAddress(&p_xh, g_xh);
    cudaGetSymbolAddress(&p_wh, g_wh);
    cudaGetSymbolAddress(&p_mask, g_mask);

    k_zero<<<(MASK_WORDS + 255) / 256, 256>>>((uint32_t*)p_mask, MASK_WORDS);

    int n4x = MDIM * KDIM / 4;
    int n4w = NDIM * KDIM / 4;
    k_cvt<<<(n4x + 255) / 256, 256>>>(x, (__half*)p_xh, n4x);
    k_cvt<<<(n4w + 255) / 256, 256>>>(w, (__half*)p_wh, n4w);
    k_mask<<<(256 * 256 * 32) / 256, 256>>>((const __half*)p_wh, (uint32_t*)p_mask);

    static bool attr_set = false;
    if (!attr_set) {
        cudaFuncSetAttribute(k_gemm, cudaFuncAttributeMaxDynamicSharedMemorySize, SMEM_BYTES);
        attr_set = true;
    }

    int grid = (MDIM / BM) * (NDIM / BN);  // 2048
    k_gemm<<<grid, NTHREADS, SMEM_BYTES>>>((const __half*)p_xh, (const __half*)p_wh,
                                           (const uint32_t*)p_mask, bias, out);
}

// round 16
// speedup vs baseline: 1.0345x; 1.0345x over previous
#include <cuda_runtime.h>
#include <cuda_fp16.h>
#include <cstdint>

// ---------------- problem geometry ----------------
static constexpr int MDIM = 8192;
static constexpr int NDIM = 4096;
static constexpr int KDIM = 4096;

static constexpr int BM = 128;
static constexpr int BN = 128;
static constexpr int BKC = 32;               // fp16 k elems per chunk (64 B rows)
static constexpr int NKC = KDIM / BKC;       // 128 chunks
static constexpr int STAGES = 4;
static constexpr int NTHREADS = 128;         // 4 warps, warp tile 64x64

static constexpr int ROW_B = 64;                         // 64 B per row, no padding
static constexpr int A_TILE_B = BM * ROW_B;              // 8192 bytes
static constexpr int B_TILE_B = BN * ROW_B;              // 8192 bytes
static constexpr int STAGE_B = A_TILE_B + B_TILE_B;      // 16384
static constexpr int MASK_WORDS = 256 * 8;               // [k_block][o_word] bits over o
static constexpr int MASK_B = MASK_WORDS * 4;            // 8192 bytes
static constexpr int SMEM_BYTES = STAGES * STAGE_B + MASK_B;  // 73728 -> 2 CTAs/SM

// ---------------- device scratch (allocation-free) ----------------
static __device__ __half g_xh[(size_t)MDIM * KDIM];
static __device__ __half g_wh[(size_t)NDIM * KDIM];
static __device__ uint32_t g_mask[MASK_WORDS];

// ---------------- PTX helpers (base-target, sm_80-era) ----------------
__device__ __forceinline__ uint32_t smem_u32(const void* p) {
    uint32_t a;
    asm("{ .reg .u64 t; cvta.to.shared.u64 t, %1; cvt.u32.u64 %0, t; }" : "=r"(a) : "l"(p));
    return a;
}

#define CP_ASYNC16(dst, src) \
    asm volatile("cp.async.cg.shared.global [%0], [%1], 16;" :: "r"(dst), "l"(src) : "memory")
#define CP_COMMIT() asm volatile("cp.async.commit_group;" ::: "memory")
#define CP_WAIT(n)  asm volatile("cp.async.wait_group %0;" :: "n"(n) : "memory")

#define LDSM4(r0, r1, r2, r3, addr)                                        \
    asm volatile("ldmatrix.sync.aligned.m8n8.x4.shared.b16 {%0,%1,%2,%3}, [%4];" \
                 : "=r"(r0), "=r"(r1), "=r"(r2), "=r"(r3) : "r"(addr))

#define MMA16816(c, a, b0, b1)                                             \
    asm volatile(                                                          \
        "mma.sync.aligned.m16n8k16.row.col.f32.f16.f16.f32 "               \
        "{%0,%1,%2,%3}, {%4,%5,%6,%7}, {%8,%9}, {%0,%1,%2,%3};"            \
        : "+f"((c)[0]), "+f"((c)[1]), "+f"((c)[2]), "+f"((c)[3])           \
        : "r"((a)[0]), "r"((a)[1]), "r"((a)[2]), "r"((a)[3]),              \
          "r"(b0), "r"(b1))

// ---------------- zero kernel (capture-safe; no memset API) ----------------
__global__ void __launch_bounds__(256) k_zero(uint32_t* __restrict__ p, int n) {
    int i = blockIdx.x * blockDim.x + threadIdx.x;
    if (i < n) p[i] = 0u;
}

// ---------------- conversion kernel: fp32 -> fp16 ----------------
__global__ void __launch_bounds__(256) k_cvt(const float* __restrict__ src,
                                             __half* __restrict__ dst, int n4) {
    int i = blockIdx.x * blockDim.x + threadIdx.x;
    if (i >= n4) return;
    float4 v = reinterpret_cast<const float4*>(src)[i];
    __half2 p0(__float2half_rn(v.x), __float2half_rn(v.y));
    __half2 p1(__float2half_rn(v.z), __float2half_rn(v.w));
    uint2 o;
    o.x = *reinterpret_cast<uint32_t*>(&p0);
    o.y = *reinterpret_cast<uint32_t*>(&p1);
    reinterpret_cast<uint2*>(dst)[i] = o;
}

// ---------------- block-mask kernel (fp16 input): one warp per 16x16 block ----------------
__global__ void __launch_bounds__(256) k_mask(const __half* __restrict__ wh,
                                              uint32_t* __restrict__ maskT) {
    int wg = (blockIdx.x * blockDim.x + threadIdx.x) >> 5;   // 0 .. 65535
    if (wg >= 256 * 256) return;
    int ob = wg >> 8;      // output-feature block (row block of W)
    int kb = wg & 255;     // k block (col block of W)
    int lane = threadIdx.x & 31;
    const __half* base = wh + (size_t)(ob * 16 + (lane >> 1)) * KDIM + kb * 16 + (lane & 1) * 8;
    uint4 v = *reinterpret_cast<const uint4*>(base);
    uint32_t nzw = (v.x | v.y | v.z | v.w) & 0x7FFF7FFFu;   // ignore sign bits (-0.0)
    uint32_t ball = __ballot_sync(0xFFFFFFFFu, nzw != 0u);
    if (lane == 0 && ball)
        atomicOr(&maskT[kb * 8 + (ob >> 5)], 1u << (ob & 31));
}

// ---------------- GEMM: 4 warps x (64x64), swizzled smem, half-warp-uniform B skip ----------------
__global__ void __launch_bounds__(NTHREADS, 2) k_gemm(
    const __half* __restrict__ xh, const __half* __restrict__ wh,
    const uint32_t* __restrict__ maskT,
    const float* __restrict__ bias, float* __restrict__ out) {
    extern __shared__ char smem[];
    const uint32_t sb = smem_u32(smem);
    uint32_t* s_mask = reinterpret_cast<uint32_t*>(smem + STAGES * STAGE_B);

    const int tid = threadIdx.x;
    const int wid = tid >> 5;     // 0..3
    const int lane = tid & 31;
    const int warp_m = wid & 1;   // 0..1 -> 64 rows
    const int warp_n = wid >> 1;  // 0..1 -> 64 cols

    // tile mapping with L2 supergrouping
    constexpr int NPN = NDIM / BN;  // 32
    constexpr int GROUP_M = 8;
    int pid = blockIdx.x;
    int npg = GROUP_M * NPN;        // 256
    int pm = (pid / npg) * GROUP_M + (pid % npg) % GROUP_M;
    int pn = (pid % npg) / GROUP_M;

    // producer mapping: half-warp-uniform k-block, warp-uniform o-block per iteration
    const int ldseg = (lane >> 3) & 3;             // 0..3, uniform per 8 lanes
    const int ldrow = wid * 8 + (lane & 7);        // 0..31
    // swizzled destination segment (r0 multiples of 32 keep (r>>1)&3 invariant)
    const uint32_t st_off = (uint32_t)((ldseg ^ ((ldrow >> 1) & 3)) * 16);

    // per-thread B-block mask addressing (uniform per half-warp):
    const int m_sks = ldseg >> 1;                  // k-block within chunk
    const int m_word = pn >> 2;
    const int m_shb = (pn & 3) * 8 + (ldrow >> 4); // + r0/16 per load

    auto a_s = [&](int s) { return sb + (uint32_t)s * STAGE_B; };
    auto b_s = [&](int s) { return sb + (uint32_t)s * STAGE_B + A_TILE_B; };

    const __half* gA = xh + (size_t)(pm * BM) * KDIM;
    const __half* gB = wh + (size_t)(pn * BN) * KDIM;

    // stage the block mask (2048 words) into smem BEFORE any issue_stage reads it
    #pragma unroll
    for (int i = 0; i < MASK_WORDS / NTHREADS; i++)
        s_mask[i * NTHREADS + tid] = maskT[i * NTHREADS + tid];
    __syncthreads();

    auto issue_stage = [&](int it, int buf) {
        if (it < NKC) {
            int k0 = it * BKC;
            uint32_t dsta = a_s(buf), dstb = b_s(buf);
            uint32_t mw = s_mask[(it * 2 + m_sks) * 8 + m_word];
            #pragma unroll
            for (int r0 = 0; r0 < BM; r0 += 32) {
                int r = r0 + ldrow;
                uint32_t doff = (uint32_t)(r * ROW_B) + st_off;
                CP_ASYNC16(dsta + doff, gA + (size_t)r * KDIM + k0 + ldseg * 8);
                // skip B load when its 16x16 block is zero; predicate is half-warp uniform
                if ((mw >> (m_shb + r0 / 16)) & 1u)
                    CP_ASYNC16(dstb + doff, gB + (size_t)r * KDIM + k0 + ldseg * 8);
            }
        }
        CP_COMMIT();
    };

    // ---- ldmatrix lane addressing (swizzled) ----
    const int sA = ((lane & 15) >> 1) & 3;
    const uint32_t a_row_off = (uint32_t)((warp_m * 64 + (lane & 15)) * ROW_B);
    const uint32_t segA_ks0 = (uint32_t)((((lane >> 4)) ^ sA) * 16);
    const uint32_t segA_ks1 = (uint32_t)(((2 + (lane >> 4)) ^ sA) * 16);
    const int sB = ((((lane >> 4) * 8) + (lane & 7)) >> 1) & 3;
    const uint32_t b_row_off =
        (uint32_t)((warp_n * 64 + (lane >> 4) * 8 + (lane & 7)) * ROW_B);
    const uint32_t segB_ks0 = (uint32_t)(((((lane >> 3) & 1)) ^ sB) * 16);
    const uint32_t segB_ks1 = (uint32_t)(((2 + ((lane >> 3) & 1)) ^ sB) * 16);

    // warp's o-block word index and bit shift (4 consecutive bits, never straddles)
    const int nblk0 = pn * 8 + warp_n * 4;
    const int word_idx = nblk0 >> 5;
    const int sh = nblk0 & 31;

    float acc[4][8][4];
    #pragma unroll
    for (int i = 0; i < 4; i++)
        #pragma unroll
        for (int j = 0; j < 8; j++)
            #pragma unroll
            for (int t = 0; t < 4; t++) acc[i][j][t] = 0.0f;

    #pragma unroll
    for (int s = 0; s < STAGES - 1; s++) issue_stage(s, s);

    for (int it = 0; it < NKC; ++it) {
        CP_WAIT(STAGES - 2);
        __syncthreads();

        // fetch mask words early (off the MMA critical path)
        uint32_t bits0 = (s_mask[(it * 2 + 0) * 8 + word_idx] >> sh) & 15u;
        uint32_t bits1 = (s_mask[(it * 2 + 1) * 8 + word_idx] >> sh) & 15u;

        issue_stage(it + STAGES - 1, (it + STAGES - 1) % STAGES);

        int buf = it % STAGES;
        uint32_t Ab = a_s(buf);
        uint32_t Bb = b_s(buf);

        #pragma unroll
        for (int ks = 0; ks < 2; ks++) {
            const uint32_t bits = ks ? bits1 : bits0;
            const uint32_t segA = ks ? segA_ks1 : segA_ks0;
            const uint32_t segB = ks ? segB_ks1 : segB_ks0;

            // dense LDSM stream (stale B data for skipped blocks is never consumed)
            uint32_t br[4][4];
            #pragma unroll
            for (int p = 0; p < 4; p++)
                LDSM4(br[p][0], br[p][1], br[p][2], br[p][3],
                      Bb + b_row_off + (uint32_t)(p * 16 * ROW_B) + segB);

            uint32_t ar[4][4];
            #pragma unroll
            for (int ms = 0; ms < 4; ms++)
                LDSM4(ar[ms][0], ar[ms][1], ar[ms][2], ar[ms][3],
                      Ab + a_row_off + (uint32_t)(ms * 16 * ROW_B) + segA);

            // predicated compute: skip 8-MMA group when the 16x16 weight block is zero
            #pragma unroll
            for (int p = 0; p < 4; p++) {
                if (bits & (1u << p)) {
                    #pragma unroll
                    for (int ms = 0; ms < 4; ms++) {
                        MMA16816(acc[ms][2 * p],     ar[ms], br[p][0], br[p][1]);
                        MMA16816(acc[ms][2 * p + 1], ar[ms], br[p][2], br[p][3]);
                    }
                }
            }
        }
    }

    // epilogue: acc + bias -> out
    const int m_base = pm * BM + warp_m * 64 + (lane >> 2);
    const int n_base = pn * BN + warp_n * 64 + (lane & 3) * 2;
    #pragma unroll
    for (int ns = 0; ns < 8; ns++) {
        int col = n_base + ns * 8;
        float bv0 = __ldg(&bias[col]);
        float bv1 = __ldg(&bias[col + 1]);
        #pragma unroll
        for (int ms = 0; ms < 4; ms++) {
            int r0 = m_base + ms * 16;
            float2 v0, v1;
            v0.x = acc[ms][ns][0] + bv0;
            v0.y = acc[ms][ns][1] + bv1;
            v1.x = acc[ms][ns][2] + bv0;
            v1.y = acc[ms][ns][3] + bv1;
            *reinterpret_cast<float2*>(out + (size_t)r0 * NDIM + col) = v0;
            *reinterpret_cast<float2*>(out + (size_t)(r0 + 8) * NDIM + col) = v1;
        }
    }
}

// ---------------- host side ----------------
extern "C" void kernel_launch(void* const* d_in, const int* in_sizes, int n_in,
                              void* d_out, int out_size) {
    const float* x    = (const float*)d_in[0];
    const float* w    = (const float*)d_in[1];
    const float* bias = (const float*)d_in[2];
    float* out        = (float*)d_out;

    void *p_xh, *p_wh, *p_mask;
    cudaGetSymbolAddress(&p_xh, g_xh);
    cudaGetSymbolAddress(&p_wh, g_wh);
    cudaGetSymbolAddress(&p_mask, g_mask);

    k_zero<<<(MASK_WORDS + 255) / 256, 256>>>((uint32_t*)p_mask, MASK_WORDS);

    int n4x = MDIM * KDIM / 4;
    int n4w = NDIM * KDIM / 4;
    k_cvt<<<(n4x + 255) / 256, 256>>>(x, (__half*)p_xh, n4x);
    k_cvt<<<(n4w + 255) / 256, 256>>>(w, (__half*)p_wh, n4w);
    k_mask<<<(256 * 256 * 32) / 256, 256>>>((const __half*)p_wh, (uint32_t*)p_mask);

    static bool attr_set = false;
    if (!attr_set) {
        cudaFuncSetAttribute(k_gemm, cudaFuncAttributeMaxDynamicSharedMemorySize, SMEM_BYTES);
        attr_set = true;
    }

    int grid = (MDIM / BM) * (NDIM / BN);  // 2048
    k_gemm<<<grid, NTHREADS, SMEM_BYTES>>>((const __half*)p_xh, (const __half*)p_wh,
                                           (const uint32_t*)p_mask, bias, out);
}

// round 17
// speedup vs baseline: 1.1484x; 1.1100x over previous
#include <cuda_runtime.h>
#include <cuda_fp16.h>
#include <cstdint>

// ---------------- problem geometry ----------------
static constexpr int MDIM = 8192;
static constexpr int NDIM = 4096;
static constexpr int KDIM = 4096;

static constexpr int BM = 128;
static constexpr int BN = 128;
static constexpr int BKC = 64;               // fp16 k elems per chunk (128 B rows)
static constexpr int NKC = KDIM / BKC;       // 64 chunks
static constexpr int STAGES = 3;
static constexpr int NTHREADS = 128;         // 4 warps, warp tile 64x64

static constexpr int ROW_B = 128;                        // 128 B per row
static constexpr int A_TILE_B = BM * ROW_B;              // 16384 bytes
static constexpr int B_TILE_B = BN * ROW_B;              // 16384 bytes
static constexpr int STAGE_B = A_TILE_B + B_TILE_B;      // 32768
static constexpr int SMEM_BYTES = STAGES * STAGE_B;      // 98304 -> 2 CTAs/SM

// ---------------- device scratch (allocation-free) ----------------
static __device__ __half g_xh[(size_t)MDIM * KDIM];
static __device__ __half g_wh[(size_t)NDIM * KDIM];

// ---------------- PTX helpers (base-target, sm_80-era) ----------------
__device__ __forceinline__ uint32_t smem_u32(const void* p) {
    uint32_t a;
    asm("{ .reg .u64 t; cvta.to.shared.u64 t, %1; cvt.u32.u64 %0, t; }" : "=r"(a) : "l"(p));
    return a;
}

#define CP_ASYNC16(dst, src) \
    asm volatile("cp.async.cg.shared.global [%0], [%1], 16;" :: "r"(dst), "l"(src) : "memory")
#define CP_COMMIT() asm volatile("cp.async.commit_group;" ::: "memory")
#define CP_WAIT(n)  asm volatile("cp.async.wait_group %0;" :: "n"(n) : "memory")

#define LDSM4(r0, r1, r2, r3, addr)                                        \
    asm volatile("ldmatrix.sync.aligned.m8n8.x4.shared.b16 {%0,%1,%2,%3}, [%4];" \
                 : "=r"(r0), "=r"(r1), "=r"(r2), "=r"(r3) : "r"(addr))

#define MMA16816(c, a, b0, b1)                                             \
    asm volatile(                                                          \
        "mma.sync.aligned.m16n8k16.row.col.f32.f16.f16.f32 "               \
        "{%0,%1,%2,%3}, {%4,%5,%6,%7}, {%8,%9}, {%0,%1,%2,%3};"            \
        : "+f"((c)[0]), "+f"((c)[1]), "+f"((c)[2]), "+f"((c)[3])           \
        : "r"((a)[0]), "r"((a)[1]), "r"((a)[2]), "r"((a)[3]),              \
          "r"(b0), "r"(b1))

// ---------------- conversion kernel: fp32 -> fp16 ----------------
__global__ void __launch_bounds__(256) k_cvt(const float* __restrict__ src,
                                             __half* __restrict__ dst, int n4) {
    int i = blockIdx.x * blockDim.x + threadIdx.x;
    if (i >= n4) return;
    float4 v = reinterpret_cast<const float4*>(src)[i];
    __half2 p0(__float2half_rn(v.x), __float2half_rn(v.y));
    __half2 p1(__float2half_rn(v.z), __float2half_rn(v.w));
    uint2 o;
    o.x = *reinterpret_cast<uint32_t*>(&p0);
    o.y = *reinterpret_cast<uint32_t*>(&p1);
    reinterpret_cast<uint2*>(dst)[i] = o;
}

// ---------------- GEMM: 4 warps x (64x64), 128B-row XOR swizzle, dense ----------------
__global__ void __launch_bounds__(NTHREADS, 2) k_gemm(
    const __half* __restrict__ xh, const __half* __restrict__ wh,
    const float* __restrict__ bias, float* __restrict__ out) {
    extern __shared__ char smem[];
    const uint32_t sb = smem_u32(smem);

    const int tid = threadIdx.x;
    const int wid = tid >> 5;     // 0..3
    const int lane = tid & 31;
    const int warp_m = wid & 1;   // 0..1 -> 64 rows
    const int warp_n = wid >> 1;  // 0..1 -> 64 cols

    // tile mapping with L2 supergrouping
    constexpr int NPN = NDIM / BN;  // 32
    constexpr int GROUP_M = 8;
    int pid = blockIdx.x;
    int npg = GROUP_M * NPN;        // 256
    int pm = (pid / npg) * GROUP_M + (pid % npg) % GROUP_M;
    int pn = (pid % npg) / GROUP_M;

    // producer mapping: 8 threads per 128B row, 16 rows per pass
    const int ldseg = tid & 7;            // 16B segment in row
    const int ldrow = tid >> 3;           // 0..15
    // swizzled write segment: seg' = seg ^ (row&7); row = r0 + ldrow, r0 % 16 == 0
    const uint32_t st_off = (uint32_t)((ldseg ^ (ldrow & 7)) * 16);

    auto a_s = [&](int s) { return sb + (uint32_t)s * STAGE_B; };
    auto b_s = [&](int s) { return sb + (uint32_t)s * STAGE_B + A_TILE_B; };

    const __half* gA = xh + (size_t)(pm * BM) * KDIM;
    const __half* gB = wh + (size_t)(pn * BN) * KDIM;

    auto issue_stage = [&](int it, int buf) {
        if (it < NKC) {
            int k0 = it * BKC;
            uint32_t dsta = a_s(buf), dstb = b_s(buf);
            #pragma unroll
            for (int r0 = 0; r0 < BM; r0 += 16) {
                int r = r0 + ldrow;
                uint32_t doff = (uint32_t)(r * ROW_B) + st_off;
                CP_ASYNC16(dsta + doff, gA + (size_t)r * KDIM + k0 + ldseg * 8);
                CP_ASYNC16(dstb + doff, gB + (size_t)r * KDIM + k0 + ldseg * 8);
            }
        }
        CP_COMMIT();
    };

    // ---- ldmatrix lane addressing (swizzled, per-lane constants) ----
    // A: row = warp_m*64 + ms*16 + (lane&15); seg base = ks*2 + (lane>>4); xor = lane&7
    const uint32_t a_row_off = (uint32_t)((warp_m * 64 + (lane & 15)) * ROW_B);
    uint32_t segA[4], segB[4];
    #pragma unroll
    for (int ks = 0; ks < 4; ks++) {
        segA[ks] = (uint32_t)((((ks * 2) + (lane >> 4)) ^ (lane & 7)) * 16);
        segB[ks] = (uint32_t)((((ks * 2) + ((lane >> 3) & 1)) ^ (lane & 7)) * 16);
    }
    // B: row = warp_n*64 + p*16 + (lane>>4)*8 + (lane&7)   (row&7 == lane&7)
    const uint32_t b_row_off =
        (uint32_t)((warp_n * 64 + (lane >> 4) * 8 + (lane & 7)) * ROW_B);

    float acc[4][8][4];
    #pragma unroll
    for (int i = 0; i < 4; i++)
        #pragma unroll
        for (int j = 0; j < 8; j++)
            #pragma unroll
            for (int t = 0; t < 4; t++) acc[i][j][t] = 0.0f;

    #pragma unroll
    for (int s = 0; s < STAGES - 1; s++) issue_stage(s, s);

    for (int it = 0; it < NKC; ++it) {
        CP_WAIT(STAGES - 2);
        __syncthreads();

        issue_stage(it + STAGES - 1, (it + STAGES - 1) % STAGES);

        int buf = it % STAGES;
        uint32_t Ab = a_s(buf);
        uint32_t Bb = b_s(buf);

        #pragma unroll
        for (int ks = 0; ks < 4; ks++) {
            uint32_t br[4][4];
            #pragma unroll
            for (int p = 0; p < 4; p++)
                LDSM4(br[p][0], br[p][1], br[p][2], br[p][3],
                      Bb + b_row_off + (uint32_t)(p * 16 * ROW_B) + segB[ks]);

            uint32_t ar[4][4];
            #pragma unroll
            for (int ms = 0; ms < 4; ms++)
                LDSM4(ar[ms][0], ar[ms][1], ar[ms][2], ar[ms][3],
                      Ab + a_row_off + (uint32_t)(ms * 16 * ROW_B) + segA[ks]);

            #pragma unroll
            for (int p = 0; p < 4; p++)
                #pragma unroll
                for (int ms = 0; ms < 4; ms++) {
                    MMA16816(acc[ms][2 * p],     ar[ms], br[p][0], br[p][1]);
                    MMA16816(acc[ms][2 * p + 1], ar[ms], br[p][2], br[p][3]);
                }
        }
    }

    // epilogue: acc + bias -> out
    const int m_base = pm * BM + warp_m * 64 + (lane >> 2);
    const int n_base = pn * BN + warp_n * 64 + (lane & 3) * 2;
    #pragma unroll
    for (int ns = 0; ns < 8; ns++) {
        int col = n_base + ns * 8;
        float bv0 = __ldg(&bias[col]);
        float bv1 = __ldg(&bias[col + 1]);
        #pragma unroll
        for (int ms = 0; ms < 4; ms++) {
            int r0 = m_base + ms * 16;
            float2 v0, v1;
            v0.x = acc[ms][ns][0] + bv0;
            v0.y = acc[ms][ns][1] + bv1;
            v1.x = acc[ms][ns][2] + bv0;
            v1.y = acc[ms][ns][3] + bv1;
            *reinterpret_cast<float2*>(out + (size_t)r0 * NDIM + col) = v0;
            *reinterpret_cast<float2*>(out + (size_t)(r0 + 8) * NDIM + col) = v1;
        }
    }
}

// ---------------- host side ----------------
extern "C" void kernel_launch(void* const* d_in, const int* in_sizes, int n_in,
                              void* d_out, int out_size) {
    const float* x    = (const float*)d_in[0];
    const float* w    = (const float*)d_in[1];
    const float* bias = (const float*)d_in[2];
    float* out        = (float*)d_out;

    void *p_xh, *p_wh;
    cudaGetSymbolAddress(&p_xh, g_xh);
    cudaGetSymbolAddress(&p_wh, g_wh);

    int n4x = MDIM * KDIM / 4;
    int n4w = NDIM * KDIM / 4;
    k_cvt<<<(n4x + 255) / 256, 256>>>(x, (__half*)p_xh, n4x);
    k_cvt<<<(n4w + 255) / 256, 256>>>(w, (__half*)p_wh, n4w);

    static bool attr_set = false;
    if (!attr_set) {
        cudaFuncSetAttribute(k_gemm, cudaFuncAttributeMaxDynamicSharedMemorySize, SMEM_BYTES);
        attr_set = true;
    }

    int grid = (MDIM / BM) * (NDIM / BN);  // 2048
    k_gemm<<<grid, NTHREADS, SMEM_BYTES>>>((const __half*)p_xh, (const __half*)p_wh,
                                           bias, out);
}